// round 11
// baseline (speedup 1.0000x reference)
#include <cuda_runtime.h>
#include <cuda_fp16.h>
#include <math.h>
#include <stdint.h>

#define S_LEN 4096
#define B_DIM 32
#define H_DIM 512
#define NROW  (S_LEN * B_DIM)   // 131072
#define NUNITS 4096             // 32-row units

// ---------------- device scratch ----------------
__device__ __half g_Bh[H_DIM * H_DIM];   // fp16 hi(W[k][n]) transposed [n][k]
__device__ __half g_Bl[H_DIM * H_DIM];   // fp16 lo
__device__ unsigned g_cnt;               // dynamic tile counter (reset by split_w)

__device__ __forceinline__ uint32_t smem_u32(const void* p) {
    uint32_t a;
    asm("{ .reg .u64 t; cvta.to.shared.u64 t, %1; cvt.u32.u64 %0, t; }" : "=r"(a) : "l"(p));
    return a;
}

#define BAR1() asm volatile("bar.sync 1, 256;" ::: "memory")
#define BAR2() asm volatile("bar.sync 2, 128;" ::: "memory")

#define LDSM4(r0, r1, r2, r3, addr) \
    asm volatile("ldmatrix.sync.aligned.m8n8.x4.shared.b16 {%0,%1,%2,%3}, [%4];" \
        : "=r"(r0), "=r"(r1), "=r"(r2), "=r"(r3) : "r"(addr))

#define MMA16816(c, a, b0, b1) \
    asm volatile("mma.sync.aligned.m16n8k16.row.col.f32.f16.f16.f32 " \
        "{%0,%1,%2,%3}, {%4,%5,%6,%7}, {%8,%9}, {%0,%1,%2,%3};" \
        : "+f"((c)[0]), "+f"((c)[1]), "+f"((c)[2]), "+f"((c)[3]) \
        : "r"((a)[0]), "r"((a)[1]), "r"((a)[2]), "r"((a)[3]), "r"(b0), "r"(b1))

// packed fp32x2 helpers (FFMA2 path)
__device__ __forceinline__ unsigned long long pk2(float x, float y) {
    unsigned long long r;
    asm("mov.b64 %0, {%1, %2};" : "=l"(r) : "f"(x), "f"(y));
    return r;
}
__device__ __forceinline__ void fma2(unsigned long long &d, unsigned long long a, unsigned long long b) {
    asm("fma.rn.f32x2 %0, %1, %2, %0;" : "+l"(d) : "l"(a), "l"(b));
}
__device__ __forceinline__ float2 up2(unsigned long long v) {
    float2 r;
    asm("mov.b64 {%0, %1}, %2;" : "=f"(r.x), "=f"(r.y) : "l"(v));
    return r;
}

__device__ __forceinline__ void split4(float4 v, uint2& hi, uint2& lo) {
    __half2 h01 = __floats2half2_rn(v.x, v.y);
    __half2 h23 = __floats2half2_rn(v.z, v.w);
    float2 f01 = __half22float2(h01);
    float2 f23 = __half22float2(h23);
    __half2 l01 = __floats2half2_rn(v.x - f01.x, v.y - f01.y);
    __half2 l23 = __floats2half2_rn(v.z - f23.x, v.w - f23.y);
    hi.x = *(uint32_t*)&h01; hi.y = *(uint32_t*)&h23;
    lo.x = *(uint32_t*)&l01; lo.y = *(uint32_t*)&l23;
}

// ---------------- kernel 0: split W (transposed) + counter reset -------------
__global__ __launch_bounds__(256) void split_w(const float* __restrict__ Wm) {
    if (blockIdx.x == 0 && threadIdx.x == 0) g_cnt = 0;
    int idx = blockIdx.x * 256 + threadIdx.x;   // 0 .. 262143
    int k = idx >> 9, n = idx & 511;
    float v = Wm[idx];
    __half hi = __float2half_rn(v);
    g_Bh[n * H_DIM + k] = hi;
    g_Bl[n * H_DIM + k] = __float2half_rn(v - __half2float(hi));
}

// ---------------- SMEM layout ----------------
// tensor: per buffer 4 tiles (A_hi, A_lo, B_hi, B_lo), 128 rows x 40 halfs (80B)
#define TSTRIDE_B 80
#define TILE_B    (128 * TSTRIDE_B)   // 10240
#define BUF_B     (4 * TILE_B)        // 40960
#define T_SMEM    (2 * BUF_B)         // 81920
// fp32: As[2][16][36] f32 (4608) | Bs[2][16][128] f32 (16384)
#define F_AS      81920
#define FAST      36
#define F_BS      86528
// control
#define CTRL_T    102912
#define CTRL_F    102920
#define SMEM_ALL  102944

// ---------------- kernel 1: hybrid tensor + FMA GEMM-bilinear ----------------
// rows r = s*32+b; A[m] = Enc[r-32] (rows r<32 garbage, fixed by kernel 2)
// logit[r] = sum_n C[r,n] * Enc[r,n] * hid[b,n],  C = Enc[r-32] @ W
__global__ __launch_bounds__(384, 1) void bilinear_hybrid(
    const float* __restrict__ enc, const float* __restrict__ hid,
    const float* __restrict__ Wm, float* __restrict__ logits)
{
    extern __shared__ char smem[];
    const uint32_t sb = smem_u32(smem);
    const int tid = threadIdx.x;

    if (tid < 256) {
        // ================= tensor group: warps 0-7, 3xfp16 HMMA =================
        const int lane = tid & 31, wid = tid >> 5;
        const int warp_m = wid >> 2;     // 0..1
        const int warp_n = wid & 3;      // 0..3

        const int rrow = tid >> 3;           // 0..31
        const int c4   = (tid & 7) * 4;      // 0,4,..,28
        uint32_t asts[4];
#pragma unroll
        for (int i = 0; i < 4; ++i)
            asts[i] = (uint32_t)((rrow + i * 32) * TSTRIDE_B + c4 * 2);

        uint32_t a_addr[4];
#pragma unroll
        for (int mt = 0; mt < 4; ++mt)
            a_addr[mt] = sb + (uint32_t)((warp_m * 64 + mt * 16 + (lane & 15)) * TSTRIDE_B
                                         + ((lane >> 4) & 1) * 16);
        uint32_t b_addr[2];
#pragma unroll
        for (int p = 0; p < 2; ++p)
            b_addr[p] = sb + 2 * TILE_B +
                        (uint32_t)((warp_n * 32 + p * 16 + (lane & 15)) * TSTRIDE_B
                                   + ((lane >> 4) & 1) * 16);

        for (;;) {
            if (tid == 0)
                *(volatile unsigned*)(smem + CTRL_T) = atomicAdd(&g_cnt, 4u);
            BAR1();
            const unsigned u = *(volatile unsigned*)(smem + CTRL_T);
            if (u >= NUNITS) break;
            const int m0 = (int)u * 32;

            const float* aptr[4];
#pragma unroll
            for (int i = 0; i < 4; ++i) {
                long gr = (long)m0 + rrow + i * 32 - B_DIM;
                if (gr < 0) gr = 0;
                if (gr > NROW - 1) gr = NROW - 1;
                aptr[i] = enc + (size_t)gr * H_DIM + c4;
            }

            float rowacc[4][2];
#pragma unroll
            for (int mt = 0; mt < 4; ++mt) { rowacc[mt][0] = 0.f; rowacc[mt][1] = 0.f; }

#pragma unroll 1
            for (int nt = 0; nt < 4; ++nt) {
                const int nbase = nt * 128;

                float cacc[4][4][4];
#pragma unroll
                for (int mt = 0; mt < 4; ++mt)
#pragma unroll
                    for (int ntl = 0; ntl < 4; ++ntl)
#pragma unroll
                        for (int q = 0; q < 4; ++q) cacc[mt][ntl][q] = 0.f;

                float4 av[4];
                uint2 bh[4], bl[4];

                // prologue: stage 0 -> buf 0
#pragma unroll
                for (int i = 0; i < 4; ++i) av[i] = *(const float4*)(aptr[i]);
#pragma unroll
                for (int i = 0; i < 4; ++i) {
                    const size_t o = (size_t)(nbase + rrow + i * 32) * H_DIM + c4;
                    bh[i] = *(const uint2*)(g_Bh + o);
                    bl[i] = *(const uint2*)(g_Bl + o);
                }
                {
                    char* base = smem;
#pragma unroll
                    for (int i = 0; i < 4; ++i) {
                        uint2 hi, lo; split4(av[i], hi, lo);
                        *(uint2*)(base + asts[i])              = hi;
                        *(uint2*)(base + TILE_B + asts[i])     = lo;
                        *(uint2*)(base + 2 * TILE_B + asts[i]) = bh[i];
                        *(uint2*)(base + 3 * TILE_B + asts[i]) = bl[i];
                    }
                }
                BAR1();

#pragma unroll 1
                for (int st = 0; st < 16; ++st) {
                    const int buf = st & 1;
                    if (st < 15) {
                        const int kb = (st + 1) * 32;
#pragma unroll
                        for (int i = 0; i < 4; ++i) av[i] = *(const float4*)(aptr[i] + kb);
#pragma unroll
                        for (int i = 0; i < 4; ++i) {
                            const size_t o = (size_t)(nbase + rrow + i * 32) * H_DIM + kb + c4;
                            bh[i] = *(const uint2*)(g_Bh + o);
                            bl[i] = *(const uint2*)(g_Bl + o);
                        }
                    }

                    const uint32_t boffb = buf ? (uint32_t)BUF_B : 0u;
#pragma unroll
                    for (int kk = 0; kk < 2; ++kk) {
                        const uint32_t koff = boffb + kk * 32;
                        uint32_t afh[4][4], afl[4][4];
                        uint32_t bfh[4][2], bfl[4][2];
#pragma unroll
                        for (int mt = 0; mt < 4; ++mt)
                            LDSM4(afh[mt][0], afh[mt][1], afh[mt][2], afh[mt][3],
                                  a_addr[mt] + koff);
#pragma unroll
                        for (int p = 0; p < 2; ++p) {
                            uint32_t r0, r1, r2, r3;
                            LDSM4(r0, r1, r2, r3, b_addr[p] + koff);
                            bfh[2 * p][0] = r0;     bfh[2 * p][1] = r2;
                            bfh[2 * p + 1][0] = r1; bfh[2 * p + 1][1] = r3;
                        }
#pragma unroll
                        for (int mt = 0; mt < 4; ++mt)
#pragma unroll
                            for (int ntl = 0; ntl < 4; ++ntl)
                                MMA16816(cacc[mt][ntl], afh[mt], bfh[ntl][0], bfh[ntl][1]);
#pragma unroll
                        for (int mt = 0; mt < 4; ++mt)
                            LDSM4(afl[mt][0], afl[mt][1], afl[mt][2], afl[mt][3],
                                  a_addr[mt] + koff + TILE_B);
#pragma unroll
                        for (int mt = 0; mt < 4; ++mt)
#pragma unroll
                            for (int ntl = 0; ntl < 4; ++ntl)
                                MMA16816(cacc[mt][ntl], afl[mt], bfh[ntl][0], bfh[ntl][1]);
#pragma unroll
                        for (int p = 0; p < 2; ++p) {
                            uint32_t r0, r1, r2, r3;
                            LDSM4(r0, r1, r2, r3, b_addr[p] + koff + TILE_B);
                            bfl[2 * p][0] = r0;     bfl[2 * p][1] = r2;
                            bfl[2 * p + 1][0] = r1; bfl[2 * p + 1][1] = r3;
                        }
#pragma unroll
                        for (int mt = 0; mt < 4; ++mt)
#pragma unroll
                            for (int ntl = 0; ntl < 4; ++ntl)
                                MMA16816(cacc[mt][ntl], afh[mt], bfl[ntl][0], bfl[ntl][1]);
                    }

                    if (st < 15) {
                        char* base = smem + (buf ^ 1) * BUF_B;
#pragma unroll
                        for (int i = 0; i < 4; ++i) {
                            uint2 hi, lo; split4(av[i], hi, lo);
                            *(uint2*)(base + asts[i])              = hi;
                            *(uint2*)(base + TILE_B + asts[i])     = lo;
                            *(uint2*)(base + 2 * TILE_B + asts[i]) = bh[i];
                            *(uint2*)(base + 3 * TILE_B + asts[i]) = bl[i];
                        }
                    }
                    BAR1();
                }

                // fused epilogue: rowacc += C .* (Enc .* hid), this n-tile
#pragma unroll
                for (int mt = 0; mt < 4; ++mt) {
#pragma unroll
                    for (int j = 0; j < 2; ++j) {
                        int r = m0 + warp_m * 64 + mt * 16 + (lane >> 2) + j * 8;
                        if (r > NROW - 1) r = NROW - 1;
                        const float* er = enc + (size_t)r * H_DIM;
                        const float* hr = hid + (size_t)(r & 31) * H_DIM;
                        float acc = 0.f;
#pragma unroll
                        for (int ntl = 0; ntl < 4; ++ntl) {
                            const int col = nbase + warp_n * 32 + ntl * 8 + (lane & 3) * 2;
                            const float2 e = *(const float2*)(er + col);
                            const float2 h = *(const float2*)(hr + col);
                            acc = fmaf(cacc[mt][ntl][j * 2 + 0], e.x * h.x, acc);
                            acc = fmaf(cacc[mt][ntl][j * 2 + 1], e.y * h.y, acc);
                        }
                        rowacc[mt][j] += acc;
                    }
                }
            }

            // reduce: quad lanes -> shared rows -> global (guarded)
            float* srow = (float*)smem;
            if (tid < 128) srow[tid] = 0.f;
            BAR1();
#pragma unroll
            for (int mt = 0; mt < 4; ++mt)
#pragma unroll
                for (int j = 0; j < 2; ++j) {
                    float v = rowacc[mt][j];
                    v += __shfl_xor_sync(0xffffffffu, v, 1);
                    v += __shfl_xor_sync(0xffffffffu, v, 2);
                    if ((lane & 3) == 0)
                        atomicAdd(&srow[warp_m * 64 + mt * 16 + (lane >> 2) + j * 8], v);
                }
            BAR1();
            if (tid < 128) {
                const int r = m0 + tid;
                if (r < NROW)
                    logits[(r & 31) * S_LEN + (r >> 5)] = srow[tid];
            }
            BAR1();
        }
    } else {
        // ================= fp32 group: warps 8-11, FFMA2 path ===================
        const int tf  = tid - 256;           // 0..127
        const int frm = tf >> 4;             // 0..7 -> rows frm*4..+3
        const int fcn = tf & 15;             // cols fcn*8..+7
        const int farow = tf >> 2;           // 0..31  (A staging row)
        const int fac   = (tf & 3) * 4;      // A staging col
        const int wrow0 = tf >> 5;           // B staging rows wrow0 + 4j
        const int wc    = (tf & 31) * 4;     // B staging col

        float* As = (float*)(smem + F_AS);   // [2][16][36]
        float* Bs = (float*)(smem + F_BS);   // [2][16][128]

        for (;;) {
            if (tid == 256)
                *(volatile unsigned*)(smem + CTRL_F) = atomicAdd(&g_cnt, 1u);
            BAR2();
            const unsigned u = *(volatile unsigned*)(smem + CTRL_F);
            if (u >= NUNITS) break;
            const int m0 = (int)u * 32;

            long fgr = (long)m0 + farow - B_DIM; if (fgr < 0) fgr = 0;
            const float* fap = enc + (size_t)fgr * H_DIM + fac;

            float frow[4] = {0.f, 0.f, 0.f, 0.f};

#pragma unroll 1
            for (int nt = 0; nt < 4; ++nt) {
                const int nbase = nt * 128;

                unsigned long long c[4][4];
#pragma unroll
                for (int i = 0; i < 4; ++i)
#pragma unroll
                    for (int j = 0; j < 4; ++j) c[i][j] = 0ull;

                float4 fav;
                float4 fbv[4];

                // prologue stage 0 -> buf 0
                fav = *(const float4*)(fap);
#pragma unroll
                for (int j = 0; j < 4; ++j)
                    fbv[j] = *(const float4*)(Wm + (size_t)(wrow0 + 4 * j) * H_DIM + nbase + wc);
                As[(fac + 0) * FAST + farow] = fav.x;
                As[(fac + 1) * FAST + farow] = fav.y;
                As[(fac + 2) * FAST + farow] = fav.z;
                As[(fac + 3) * FAST + farow] = fav.w;
#pragma unroll
                for (int j = 0; j < 4; ++j)
                    *(float4*)(Bs + (wrow0 + 4 * j) * 128 + wc) = fbv[j];
                BAR2();

#pragma unroll 1
                for (int st = 0; st < 32; ++st) {
                    const int buf = st & 1;
                    if (st < 31) {
                        const int kb = (st + 1) * 16;
                        fav = *(const float4*)(fap + kb);
#pragma unroll
                        for (int j = 0; j < 4; ++j)
                            fbv[j] = *(const float4*)(Wm + (size_t)(kb + wrow0 + 4 * j) * H_DIM
                                                      + nbase + wc);
                    }
                    const float* Asb = As + buf * 16 * FAST;
                    const float* Bsb = Bs + buf * 16 * 128;
#pragma unroll
                    for (int kk = 0; kk < 16; ++kk) {
                        const float4 a = *(const float4*)(Asb + kk * FAST + frm * 4);
                        const ulonglong2 b0 = *(const ulonglong2*)(Bsb + kk * 128 + fcn * 8);
                        const ulonglong2 b1 = *(const ulonglong2*)(Bsb + kk * 128 + fcn * 8 + 4);
                        const float aa[4] = {a.x, a.y, a.z, a.w};
#pragma unroll
                        for (int i = 0; i < 4; ++i) {
                            const unsigned long long ad = pk2(aa[i], aa[i]);
                            fma2(c[i][0], ad, b0.x);
                            fma2(c[i][1], ad, b0.y);
                            fma2(c[i][2], ad, b1.x);
                            fma2(c[i][3], ad, b1.y);
                        }
                    }
                    if (st < 31) {
                        float* Asn = As + (buf ^ 1) * 16 * FAST;
                        float* Bsn = Bs + (buf ^ 1) * 16 * 128;
                        Asn[(fac + 0) * FAST + farow] = fav.x;
                        Asn[(fac + 1) * FAST + farow] = fav.y;
                        Asn[(fac + 2) * FAST + farow] = fav.z;
                        Asn[(fac + 3) * FAST + farow] = fav.w;
#pragma unroll
                        for (int j = 0; j < 4; ++j)
                            *(float4*)(Bsn + (wrow0 + 4 * j) * 128 + wc) = fbv[j];
                    }
                    BAR2();
                }

                // epilogue this n-tile
#pragma unroll
                for (int i = 0; i < 4; ++i) {
                    const int r = m0 + frm * 4 + i;
                    const float* er = enc + (size_t)r * H_DIM + nbase + fcn * 8;
                    const float* hr = hid + (size_t)(r & 31) * H_DIM + nbase + fcn * 8;
                    const float4 e0 = *(const float4*)er;
                    const float4 e1 = *(const float4*)(er + 4);
                    const float4 h0 = *(const float4*)hr;
                    const float4 h1 = *(const float4*)(hr + 4);
                    const float2 c0 = up2(c[i][0]), c1 = up2(c[i][1]);
                    const float2 c2 = up2(c[i][2]), c3 = up2(c[i][3]);
                    float s = c0.x * e0.x * h0.x + c0.y * e0.y * h0.y
                            + c1.x * e0.z * h0.z + c1.y * e0.w * h0.w
                            + c2.x * e1.x * h1.x + c2.y * e1.y * h1.y
                            + c3.x * e1.z * h1.z + c3.y * e1.w * h1.w;
                    s += __shfl_xor_sync(0xffffffffu, s, 8);
                    s += __shfl_xor_sync(0xffffffffu, s, 4);
                    s += __shfl_xor_sync(0xffffffffu, s, 2);
                    s += __shfl_xor_sync(0xffffffffu, s, 1);
                    frow[i] += s;   // valid on fcn==0 lanes
                }
            }

            if (fcn == 0) {
#pragma unroll
                for (int i = 0; i < 4; ++i) {
                    const int r = m0 + frm * 4 + i;
                    logits[(r & 31) * S_LEN + (r >> 5)] = frow[i];
                }
            }
            BAR2();
        }
    }
}

// ---------------- kernel 2: affect term + s==0 fixup + softmax ----------------
__global__ __launch_bounds__(256) void softmax_finalize(
    const float* __restrict__ enc, const float* __restrict__ hid,
    const float* __restrict__ emb, const float* __restrict__ aff,
    float* __restrict__ out)
{
    const int b = blockIdx.x;
    const int tid = threadIdx.x;
    const int lane = tid & 31, wid = tid >> 5;
    __shared__ float red[8][4];
    __shared__ float fin[4];
    __shared__ float rmax[8];
    __shared__ float rsum[8];

    float a0 = 0.f, a1 = 0.f, a2 = 0.f, e0 = 0.f;
    for (int h = tid; h < H_DIM; h += 256) {
        const float hv = hid[b * H_DIM + h];
        a0 += hv * aff[h * 3 + 0];
        a1 += hv * aff[h * 3 + 1];
        a2 += hv * aff[h * 3 + 2];
        e0 += hv * enc[b * H_DIM + h];
    }
#pragma unroll
    for (int m = 16; m; m >>= 1) {
        a0 += __shfl_xor_sync(~0u, a0, m);
        a1 += __shfl_xor_sync(~0u, a1, m);
        a2 += __shfl_xor_sync(~0u, a2, m);
        e0 += __shfl_xor_sync(~0u, e0, m);
    }
    if (lane == 0) { red[wid][0] = a0; red[wid][1] = a1; red[wid][2] = a2; red[wid][3] = e0; }
    __syncthreads();
    if (tid < 4) {
        float s = 0.f;
        for (int w = 0; w < 8; ++w) s += red[w][tid];
        fin[tid] = s;
    }
    __syncthreads();
    const float A0 = fin[0], A1 = fin[1], A2 = fin[2], E0 = fin[3];

    float l[16];
    float mx = -INFINITY;
#pragma unroll
    for (int it = 0; it < 16; ++it) {
        const int s = tid + it * 256;
        float v = (s == 0) ? E0 : out[b * S_LEN + s];
        const float* ep = emb + ((size_t)s * B_DIM + b) * 3;
        v += A0 * ep[0] + A1 * ep[1] + A2 * ep[2];
        l[it] = v;
        mx = fmaxf(mx, v);
    }
#pragma unroll
    for (int m = 16; m; m >>= 1) mx = fmaxf(mx, __shfl_xor_sync(~0u, mx, m));
    if (lane == 0) rmax[wid] = mx;
    __syncthreads();
    if (tid == 0) {
        float m2 = rmax[0];
        for (int w = 1; w < 8; ++w) m2 = fmaxf(m2, rmax[w]);
        rmax[0] = m2;
    }
    __syncthreads();
    const float MX = rmax[0];

    float sum = 0.f;
#pragma unroll
    for (int it = 0; it < 16; ++it) { l[it] = expf(l[it] - MX); sum += l[it]; }
#pragma unroll
    for (int m = 16; m; m >>= 1) sum += __shfl_xor_sync(~0u, sum, m);
    if (lane == 0) rsum[wid] = sum;
    __syncthreads();
    if (tid == 0) {
        float s2 = 0.f;
        for (int w = 0; w < 8; ++w) s2 += rsum[w];
        rsum[0] = s2;
    }
    __syncthreads();
    const float inv = 1.0f / rsum[0];
#pragma unroll
    for (int it = 0; it < 16; ++it)
        out[b * S_LEN + tid + it * 256] = l[it] * inv;
}

// ---------------- launch ----------------
extern "C" void kernel_launch(void* const* d_in, const int* in_sizes, int n_in,
                              void* d_out, int out_size) {
    const float *hid = nullptr, *enc = nullptr, *emb = nullptr, *Wm = nullptr, *aff = nullptr;
    for (int i = 0; i < n_in; ++i) {
        switch (in_sizes[i]) {
            case 16384:    hid = (const float*)d_in[i]; break;  // hidden [1,32,512]
            case 67108864: enc = (const float*)d_in[i]; break;  // encoder_outputs [4096,32,512]
            case 393216:   emb = (const float*)d_in[i]; break;  // embedding [4096,32,3]
            case 262144:   Wm  = (const float*)d_in[i]; break;  // bigram_matrix [512,512]
            case 1536:     aff = (const float*)d_in[i]; break;  // affect_matrix [512,3]
        }
    }
    float* out = (float*)d_out;  // [32,1,4096] fp32; logits scratch then softmax

    cudaFuncSetAttribute(bilinear_hybrid,
                         cudaFuncAttributeMaxDynamicSharedMemorySize, SMEM_ALL);

    split_w<<<(H_DIM * H_DIM) / 256, 256>>>(Wm);
    bilinear_hybrid<<<152, 384, SMEM_ALL>>>(enc, hid, Wm, out);
    softmax_finalize<<<B_DIM, 256>>>(enc, hid, emb, aff, out);
}